// round 3
// baseline (speedup 1.0000x reference)
#include <cuda_runtime.h>
#include <cuda_fp16.h>

#define NN 50000
#define NE 800000
#define HEADS 8
#define HID 16
#define H1DIM 128
#define OUTC 40
#define NEG 0.2f

// ---------------- scratch (allocation-free: __device__ globals) ----------------
__device__ __align__(16) __half2 g_h1h[NN * 64];   // layer1 features, fp16 pairs
__device__ float g_as1[NN * HEADS];
__device__ float g_ad1[NN * HEADS];
__device__ float g_out1[NN * H1DIM];   // layer1 aggregated + ELU (fp32)
__device__ float g_h2[NN * OUTC];
__device__ float g_as2[NN];
__device__ float g_ad2[NN];
__device__ int   g_deg[NN];
__device__ int   g_off[NN];            // after scatter: g_off[n] = END of bucket n
__device__ int   g_csrc[NE];           // CSR: src node per (dst-bucketed) edge

__device__ __forceinline__ float leaky(float v) { return v > 0.f ? v : NEG * v; }

// ---------------- init ----------------
__global__ void k_init() {
    int i = blockIdx.x * blockDim.x + threadIdx.x;
    int st = gridDim.x * blockDim.x;
    for (int j = i; j < NN; j += st) g_deg[j] = 0;
}

// ---------------- CSR build ----------------
__global__ void k_deg(const int* __restrict__ ei) {
    int e = blockIdx.x * blockDim.x + threadIdx.x;
    if (e < NE) atomicAdd(&g_deg[ei[NE + e]], 1);
}

__global__ void k_scan() {   // single block, 1024 threads: exclusive prefix into g_off
    __shared__ int sums[1024];
    int t = threadIdx.x;
    const int CH = (NN + 1023) / 1024;   // 49
    int base = t * CH;
    int local = 0;
    for (int j = 0; j < CH; j++) {
        int idx = base + j;
        if (idx < NN) local += g_deg[idx];
    }
    sums[t] = local;
    __syncthreads();
    for (int o = 1; o < 1024; o <<= 1) {
        int v = (t >= o) ? sums[t - o] : 0;
        __syncthreads();
        sums[t] += v;
        __syncthreads();
    }
    int run = (t > 0) ? sums[t - 1] : 0;
    for (int j = 0; j < CH; j++) {
        int idx = base + j;
        if (idx < NN) { g_off[idx] = run; run += g_deg[idx]; }
    }
}

// scatter bumps g_off in place: afterwards g_off[n] = end of bucket n
__global__ void k_scatter(const int* __restrict__ ei) {
    int e = blockIdx.x * blockDim.x + threadIdx.x;
    if (e >= NE) return;
    int s = ei[e], d = ei[NE + e];
    int pos = atomicAdd(&g_off[d], 1);
    g_csrc[pos] = s;
}

// ---------------- GEMM1: h1 = x @ W1 (fp16 store) + attention logits -------------
// BM=128, BN=128, BK=16, 256 threads, TM=8, TN=8
__global__ void k_gemm1(const float* __restrict__ A, const float* __restrict__ B,
                        const float* __restrict__ att_src, const float* __restrict__ att_dst) {
    __shared__ float As[16][128];
    __shared__ float Bs[16][128];
    int tid = threadIdx.x;
    int tx = tid & 15;          // cols tx*8..+8
    int ty = tid >> 4;          // rows ty*8..+8
    int row0 = blockIdx.x * 128;
    float acc[8][8] = {};
    for (int k0 = 0; k0 < 128; k0 += 16) {
#pragma unroll
        for (int p = 0; p < 2; p++) {   // A tile 128x16 -> transposed smem
            int fi = tid + p * 256;
            int r = fi >> 2;
            int kk = (fi & 3) * 4;
            int grow = row0 + r;
            float4 v = make_float4(0.f, 0.f, 0.f, 0.f);
            if (grow < NN) v = *(const float4*)&A[grow * 128 + k0 + kk];
            As[kk + 0][r] = v.x; As[kk + 1][r] = v.y;
            As[kk + 2][r] = v.z; As[kk + 3][r] = v.w;
        }
#pragma unroll
        for (int p = 0; p < 2; p++) {   // B tile 16x128
            int fi = tid + p * 256;
            int kk = fi >> 5;
            int nc = (fi & 31) * 4;
            *(float4*)&Bs[kk][nc] = *(const float4*)&B[(k0 + kk) * 128 + nc];
        }
        __syncthreads();
#pragma unroll
        for (int kk = 0; kk < 16; kk++) {
            float a[8], b[8];
#pragma unroll
            for (int i = 0; i < 8; i++) a[i] = As[kk][ty * 8 + i];
#pragma unroll
            for (int j = 0; j < 8; j++) b[j] = Bs[kk][tx * 8 + j];
#pragma unroll
            for (int i = 0; i < 8; i++)
#pragma unroll
                for (int j = 0; j < 8; j++) acc[i][j] += a[i] * b[j];
        }
        __syncthreads();
    }
    // epilogue: fp16 store + fused per-head logits (head = tx>>1)
    float ws[8], wd[8];
#pragma unroll
    for (int j = 0; j < 8; j++) { ws[j] = att_src[tx * 8 + j]; wd[j] = att_dst[tx * 8 + j]; }
#pragma unroll
    for (int i = 0; i < 8; i++) {
        int grow = row0 + ty * 8 + i;
        float ps = 0.f, pd = 0.f;
#pragma unroll
        for (int j = 0; j < 8; j++) { ps += acc[i][j] * ws[j]; pd += acc[i][j] * wd[j]; }
        if (grow < NN) {
            __half2 hh[4];
#pragma unroll
            for (int q = 0; q < 4; q++)
                hh[q] = __floats2half2_rn(acc[i][q * 2], acc[i][q * 2 + 1]);
            *(uint4*)&g_h1h[grow * 64 + tx * 4] = *(uint4*)hh;
        }
        ps += __shfl_xor_sync(0xffffffffu, ps, 1);
        pd += __shfl_xor_sync(0xffffffffu, pd, 1);
        if ((tx & 1) == 0 && grow < NN) {
            g_as1[grow * 8 + (tx >> 1)] = ps;
            g_ad1[grow * 8 + (tx >> 1)] = pd;
        }
    }
}

// ---------------- layer1: single-pass softmax-aggregate + bias + ELU ------------
// one warp per dst node; lane handles channels [lane*4, lane*4+4), head = lane>>2
__global__ void k_node1(const float* __restrict__ b1) {
    int lane = threadIdx.x & 31;
    int warp = (blockIdx.x * blockDim.x + threadIdx.x) >> 5;
    int nwarp = (gridDim.x * blockDim.x) >> 5;
    int h = lane >> 2;
    for (int n = warp; n < NN; n += nwarp) {
        int beg = (n == 0) ? 0 : g_off[n - 1];
        int end = g_off[n];
        float ad = g_ad1[n * 8 + h];
        float4 acc = make_float4(0.f, 0.f, 0.f, 0.f);
        float sum = 0.f;
#pragma unroll 2
        for (int i = beg; i < end; i++) {
            int s = g_csrc[i];
            float e = __expf(leaky(g_as1[s * 8 + h] + ad));
            sum += e;
            uint2 raw = *(const uint2*)&g_h1h[s * 64 + lane * 2];
            float2 f0 = __half22float2(((const __half2*)&raw)[0]);
            float2 f1 = __half22float2(((const __half2*)&raw)[1]);
            acc.x += e * f0.x; acc.y += e * f0.y;
            acc.z += e * f1.x; acc.w += e * f1.y;
        }
        float inv = (sum > 0.f) ? 1.f / sum : 0.f;
        float4 bv = *(const float4*)&b1[lane * 4];
        float4 o;
        o.x = acc.x * inv + bv.x; o.y = acc.y * inv + bv.y;
        o.z = acc.z * inv + bv.z; o.w = acc.w * inv + bv.w;
        o.x = o.x > 0.f ? o.x : expm1f(o.x);
        o.y = o.y > 0.f ? o.y : expm1f(o.y);
        o.z = o.z > 0.f ? o.z : expm1f(o.z);
        o.w = o.w > 0.f ? o.w : expm1f(o.w);
        *(float4*)&g_out1[n * 128 + lane * 4] = o;
    }
}

// ---------------- GEMM2: g_h2 = g_out1 @ W2, fused attention-logit epilogue -----
// BM=128, BK=16, 256 threads, TM=4, TN=5
__global__ void k_gemm2(const float* __restrict__ B,
                        const float* __restrict__ att_src, const float* __restrict__ att_dst) {
    __shared__ float As[16][128];
    __shared__ float Bs[16][40];
    int tid = threadIdx.x;
    int tx = tid & 7;
    int ty = tid >> 3;
    int row0 = blockIdx.x * 128;
    float acc[4][5] = {};
    for (int k0 = 0; k0 < 128; k0 += 16) {
#pragma unroll
        for (int p = 0; p < 2; p++) {
            int fi = tid + p * 256;
            int r = fi >> 2;
            int kk = (fi & 3) * 4;
            int grow = row0 + r;
            float4 v = make_float4(0.f, 0.f, 0.f, 0.f);
            if (grow < NN) v = *(const float4*)&g_out1[grow * 128 + k0 + kk];
            As[kk + 0][r] = v.x; As[kk + 1][r] = v.y;
            As[kk + 2][r] = v.z; As[kk + 3][r] = v.w;
        }
        if (tid < 160) {
            int kk = tid / 10;
            int nc = (tid % 10) * 4;
            *(float4*)&Bs[kk][nc] = *(const float4*)&B[(k0 + kk) * 40 + nc];
        }
        __syncthreads();
#pragma unroll
        for (int kk = 0; kk < 16; kk++) {
            float a[4], b[5];
#pragma unroll
            for (int i = 0; i < 4; i++) a[i] = As[kk][ty * 4 + i];
#pragma unroll
            for (int j = 0; j < 5; j++) b[j] = Bs[kk][tx * 5 + j];
#pragma unroll
            for (int i = 0; i < 4; i++)
#pragma unroll
                for (int j = 0; j < 5; j++) acc[i][j] += a[i] * b[j];
        }
        __syncthreads();
    }
    float ws[5], wd[5];
#pragma unroll
    for (int j = 0; j < 5; j++) { ws[j] = att_src[tx * 5 + j]; wd[j] = att_dst[tx * 5 + j]; }
#pragma unroll
    for (int i = 0; i < 4; i++) {
        int grow = row0 + ty * 4 + i;
        float ps = 0.f, pd = 0.f;
#pragma unroll
        for (int j = 0; j < 5; j++) {
            ps += acc[i][j] * ws[j];
            pd += acc[i][j] * wd[j];
            if (grow < NN) g_h2[grow * 40 + tx * 5 + j] = acc[i][j];
        }
        ps += __shfl_xor_sync(0xffffffffu, ps, 1);
        ps += __shfl_xor_sync(0xffffffffu, ps, 2);
        ps += __shfl_xor_sync(0xffffffffu, ps, 4);
        pd += __shfl_xor_sync(0xffffffffu, pd, 1);
        pd += __shfl_xor_sync(0xffffffffu, pd, 2);
        pd += __shfl_xor_sync(0xffffffffu, pd, 4);
        if (tx == 0 && grow < NN) { g_as2[grow] = ps; g_ad2[grow] = pd; }
    }
}

// ---------------- layer2: single-pass softmax-aggregate + bias → d_out ----------
__global__ void k_node2(const float* __restrict__ b2, float* __restrict__ dout) {
    int lane = threadIdx.x & 31;
    int warp = (blockIdx.x * blockDim.x + threadIdx.x) >> 5;
    int nwarp = (gridDim.x * blockDim.x) >> 5;
    for (int n = warp; n < NN; n += nwarp) {
        int beg = (n == 0) ? 0 : g_off[n - 1];
        int end = g_off[n];
        float ad = g_ad2[n];
        float4 acc = make_float4(0.f, 0.f, 0.f, 0.f);
        float sum = 0.f;
#pragma unroll 2
        for (int i = beg; i < end; i++) {
            int s = g_csrc[i];
            float e = __expf(leaky(g_as2[s] + ad));
            sum += e;
            if (lane < 10) {
                float4 hv = *(const float4*)&g_h2[s * 40 + lane * 4];
                acc.x += e * hv.x; acc.y += e * hv.y;
                acc.z += e * hv.z; acc.w += e * hv.w;
            }
        }
        float inv = (sum > 0.f) ? 1.f / sum : 0.f;
        if (lane < 10) {
            float4 bv = *(const float4*)&b2[lane * 4];
            float4 o;
            o.x = acc.x * inv + bv.x; o.y = acc.y * inv + bv.y;
            o.z = acc.z * inv + bv.z; o.w = acc.w * inv + bv.w;
            *(float4*)&dout[n * 40 + lane * 4] = o;
        }
    }
}

// ---------------- launch ----------------
extern "C" void kernel_launch(void* const* d_in, const int* in_sizes, int n_in,
                              void* d_out, int out_size) {
    const float* x   = (const float*)d_in[0];
    const int*   ei  = (const int*)d_in[1];
    const float* W1  = (const float*)d_in[2];
    const float* as1 = (const float*)d_in[3];
    const float* ad1 = (const float*)d_in[4];
    const float* b1  = (const float*)d_in[5];
    const float* W2  = (const float*)d_in[6];
    const float* as2 = (const float*)d_in[7];
    const float* ad2 = (const float*)d_in[8];
    const float* b2  = (const float*)d_in[9];
    float* out = (float*)d_out;

    k_init<<<64, 256>>>();
    k_deg<<<(NE + 255) / 256, 256>>>(ei);
    k_scan<<<1, 1024>>>();
    k_scatter<<<(NE + 255) / 256, 256>>>(ei);
    k_gemm1<<<(NN + 127) / 128, 256>>>(x, W1, as1, ad1);
    k_node1<<<(NN * 32 + 255) / 256, 256>>>(b1);
    k_gemm2<<<(NN + 127) / 128, 256>>>(W2, as2, ad2);
    k_node2<<<(NN * 32 + 255) / 256, 256>>>(b2, out);
}

// round 4
// speedup vs baseline: 1.2464x; 1.2464x over previous
#include <cuda_runtime.h>
#include <cuda_fp16.h>

#define NN 50000
#define NE 800000
#define HEADS 8
#define HID 16
#define H1DIM 128
#define OUTC 40
#define NEG 0.2f
#define NB_SCAN 200          // 200 blocks x 250 nodes = 50000

// ---------------- scratch (allocation-free: __device__ globals) ----------------
__device__ __align__(16) __half2 g_h1h[NN * 64];   // layer1 features, fp16 pairs
__device__ float g_as1[NN * HEADS];
__device__ float g_ad1[NN * HEADS];
__device__ float g_out1[NN * H1DIM];
__device__ float g_h2[NN * OUTC];
__device__ float g_as2[NN];
__device__ float g_ad2[NN];
__device__ int   g_deg[NN];
__device__ int   g_off[NN];            // start offsets; after scatter: END of bucket n
__device__ int   g_csrc[NE];
__device__ int   g_part[NB_SCAN];
__device__ int   g_base[NB_SCAN];

__device__ __forceinline__ float leaky(float v) { return v > 0.f ? v : NEG * v; }

// ---------------- init ----------------
__global__ void k_init() {
    int i = blockIdx.x * blockDim.x + threadIdx.x;
    if (i < NN) g_deg[i] = 0;
}

// ---------------- CSR build ----------------
__global__ void k_deg(const int* __restrict__ ei) {
    int e = blockIdx.x * blockDim.x + threadIdx.x;
    if (e < NE) atomicAdd(&g_deg[ei[NE + e]], 1);
}

// phase 1: per-block (250 nodes) exclusive scan + block total
__global__ void k_scan1() {
    __shared__ int sm[256];
    int b = blockIdx.x, t = threadIdx.x;
    int n = b * 250 + t;
    int v = (t < 250 && n < NN) ? g_deg[n] : 0;
    sm[t] = v;
    __syncthreads();
#pragma unroll
    for (int o = 1; o < 256; o <<= 1) {
        int u = (t >= o) ? sm[t - o] : 0;
        __syncthreads();
        sm[t] += u;
        __syncthreads();
    }
    if (t < 250 && n < NN) g_off[n] = sm[t] - v;   // exclusive within block
    if (t == 255) g_part[b] = sm[255];
}

// phase 2: scan the 200 block totals (one block)
__global__ void k_scan2() {
    __shared__ int sm[256];
    int t = threadIdx.x;
    int v = (t < NB_SCAN) ? g_part[t] : 0;
    sm[t] = v;
    __syncthreads();
#pragma unroll
    for (int o = 1; o < 256; o <<= 1) {
        int u = (t >= o) ? sm[t - o] : 0;
        __syncthreads();
        sm[t] += u;
        __syncthreads();
    }
    if (t < NB_SCAN) g_base[t] = sm[t] - v;        // exclusive base per block
}

// phase 3: add base
__global__ void k_scan3() {
    int b = blockIdx.x, t = threadIdx.x;
    int n = b * 250 + t;
    if (t < 250 && n < NN) g_off[n] += g_base[b];
}

// scatter bumps g_off in place: afterwards g_off[n] = end of bucket n
__global__ void k_scatter(const int* __restrict__ ei) {
    int e = blockIdx.x * blockDim.x + threadIdx.x;
    if (e >= NE) return;
    int s = ei[e], d = ei[NE + e];
    int pos = atomicAdd(&g_off[d], 1);
    g_csrc[pos] = s;
}

// ---------------- GEMM1: h1 = x @ W1 (fp16 store) + attention logits -------------
__global__ void k_gemm1(const float* __restrict__ A, const float* __restrict__ B,
                        const float* __restrict__ att_src, const float* __restrict__ att_dst) {
    __shared__ float As[16][128];
    __shared__ float Bs[16][128];
    int tid = threadIdx.x;
    int tx = tid & 15;
    int ty = tid >> 4;
    int row0 = blockIdx.x * 128;
    float acc[8][8] = {};
    for (int k0 = 0; k0 < 128; k0 += 16) {
#pragma unroll
        for (int p = 0; p < 2; p++) {
            int fi = tid + p * 256;
            int r = fi >> 2;
            int kk = (fi & 3) * 4;
            int grow = row0 + r;
            float4 v = make_float4(0.f, 0.f, 0.f, 0.f);
            if (grow < NN) v = *(const float4*)&A[grow * 128 + k0 + kk];
            As[kk + 0][r] = v.x; As[kk + 1][r] = v.y;
            As[kk + 2][r] = v.z; As[kk + 3][r] = v.w;
        }
#pragma unroll
        for (int p = 0; p < 2; p++) {
            int fi = tid + p * 256;
            int kk = fi >> 5;
            int nc = (fi & 31) * 4;
            *(float4*)&Bs[kk][nc] = *(const float4*)&B[(k0 + kk) * 128 + nc];
        }
        __syncthreads();
#pragma unroll
        for (int kk = 0; kk < 16; kk++) {
            float a[8], b[8];
#pragma unroll
            for (int i = 0; i < 8; i++) a[i] = As[kk][ty * 8 + i];
#pragma unroll
            for (int j = 0; j < 8; j++) b[j] = Bs[kk][tx * 8 + j];
#pragma unroll
            for (int i = 0; i < 8; i++)
#pragma unroll
                for (int j = 0; j < 8; j++) acc[i][j] += a[i] * b[j];
        }
        __syncthreads();
    }
    float ws[8], wd[8];
#pragma unroll
    for (int j = 0; j < 8; j++) { ws[j] = att_src[tx * 8 + j]; wd[j] = att_dst[tx * 8 + j]; }
#pragma unroll
    for (int i = 0; i < 8; i++) {
        int grow = row0 + ty * 8 + i;
        float ps = 0.f, pd = 0.f;
#pragma unroll
        for (int j = 0; j < 8; j++) { ps += acc[i][j] * ws[j]; pd += acc[i][j] * wd[j]; }
        if (grow < NN) {
            __half2 hh[4];
#pragma unroll
            for (int q = 0; q < 4; q++)
                hh[q] = __floats2half2_rn(acc[i][q * 2], acc[i][q * 2 + 1]);
            *(uint4*)&g_h1h[grow * 64 + tx * 4] = *(uint4*)hh;
        }
        ps += __shfl_xor_sync(0xffffffffu, ps, 1);
        pd += __shfl_xor_sync(0xffffffffu, pd, 1);
        if ((tx & 1) == 0 && grow < NN) {
            g_as1[grow * 8 + (tx >> 1)] = ps;
            g_ad1[grow * 8 + (tx >> 1)] = pd;
        }
    }
}

// ---------------- layer1: single-pass softmax-aggregate + bias + ELU ------------
// one warp per dst node; lane handles channels [lane*4,+4), head = lane>>2
// edge indices loaded warp-coalesced, broadcast via shfl
__global__ void k_node1(const float* __restrict__ b1) {
    int lane = threadIdx.x & 31;
    int warp = (blockIdx.x * blockDim.x + threadIdx.x) >> 5;
    int nwarp = (gridDim.x * blockDim.x) >> 5;
    int h = lane >> 2;
    for (int n = warp; n < NN; n += nwarp) {
        int beg = (n == 0) ? 0 : g_off[n - 1];
        int end = g_off[n];
        float ad = g_ad1[n * 8 + h];
        float4 acc = make_float4(0.f, 0.f, 0.f, 0.f);
        float sum = 0.f;
        for (int base = beg; base < end; base += 32) {
            int cnt = end - base; if (cnt > 32) cnt = 32;
            int idx = (lane < cnt) ? g_csrc[base + lane] : 0;
#pragma unroll 4
            for (int j = 0; j < cnt; j++) {
                int s = __shfl_sync(0xffffffffu, idx, j);
                float e = __expf(leaky(g_as1[s * 8 + h] + ad));
                sum += e;
                uint2 raw = *(const uint2*)&g_h1h[s * 64 + lane * 2];
                float2 f0 = __half22float2(((const __half2*)&raw)[0]);
                float2 f1 = __half22float2(((const __half2*)&raw)[1]);
                acc.x += e * f0.x; acc.y += e * f0.y;
                acc.z += e * f1.x; acc.w += e * f1.y;
            }
        }
        float inv = (sum > 0.f) ? 1.f / sum : 0.f;
        float4 bv = *(const float4*)&b1[lane * 4];
        float4 o;
        o.x = acc.x * inv + bv.x; o.y = acc.y * inv + bv.y;
        o.z = acc.z * inv + bv.z; o.w = acc.w * inv + bv.w;
        o.x = o.x > 0.f ? o.x : expm1f(o.x);
        o.y = o.y > 0.f ? o.y : expm1f(o.y);
        o.z = o.z > 0.f ? o.z : expm1f(o.z);
        o.w = o.w > 0.f ? o.w : expm1f(o.w);
        *(float4*)&g_out1[n * 128 + lane * 4] = o;
    }
}

// ---------------- GEMM2: g_h2 = g_out1 @ W2, fused attention-logit epilogue -----
__global__ void k_gemm2(const float* __restrict__ B,
                        const float* __restrict__ att_src, const float* __restrict__ att_dst) {
    __shared__ float As[16][128];
    __shared__ float Bs[16][40];
    int tid = threadIdx.x;
    int tx = tid & 7;
    int ty = tid >> 3;
    int row0 = blockIdx.x * 128;
    float acc[4][5] = {};
    for (int k0 = 0; k0 < 128; k0 += 16) {
#pragma unroll
        for (int p = 0; p < 2; p++) {
            int fi = tid + p * 256;
            int r = fi >> 2;
            int kk = (fi & 3) * 4;
            int grow = row0 + r;
            float4 v = make_float4(0.f, 0.f, 0.f, 0.f);
            if (grow < NN) v = *(const float4*)&g_out1[grow * 128 + k0 + kk];
            As[kk + 0][r] = v.x; As[kk + 1][r] = v.y;
            As[kk + 2][r] = v.z; As[kk + 3][r] = v.w;
        }
        if (tid < 160) {
            int kk = tid / 10;
            int nc = (tid % 10) * 4;
            *(float4*)&Bs[kk][nc] = *(const float4*)&B[(k0 + kk) * 40 + nc];
        }
        __syncthreads();
#pragma unroll
        for (int kk = 0; kk < 16; kk++) {
            float a[4], b[5];
#pragma unroll
            for (int i = 0; i < 4; i++) a[i] = As[kk][ty * 4 + i];
#pragma unroll
            for (int j = 0; j < 5; j++) b[j] = Bs[kk][tx * 5 + j];
#pragma unroll
            for (int i = 0; i < 4; i++)
#pragma unroll
                for (int j = 0; j < 5; j++) acc[i][j] += a[i] * b[j];
        }
        __syncthreads();
    }
    float ws[5], wd[5];
#pragma unroll
    for (int j = 0; j < 5; j++) { ws[j] = att_src[tx * 5 + j]; wd[j] = att_dst[tx * 5 + j]; }
#pragma unroll
    for (int i = 0; i < 4; i++) {
        int grow = row0 + ty * 4 + i;
        float ps = 0.f, pd = 0.f;
#pragma unroll
        for (int j = 0; j < 5; j++) {
            ps += acc[i][j] * ws[j];
            pd += acc[i][j] * wd[j];
            if (grow < NN) g_h2[grow * 40 + tx * 5 + j] = acc[i][j];
        }
        ps += __shfl_xor_sync(0xffffffffu, ps, 1);
        ps += __shfl_xor_sync(0xffffffffu, ps, 2);
        ps += __shfl_xor_sync(0xffffffffu, ps, 4);
        pd += __shfl_xor_sync(0xffffffffu, pd, 1);
        pd += __shfl_xor_sync(0xffffffffu, pd, 2);
        pd += __shfl_xor_sync(0xffffffffu, pd, 4);
        if (tx == 0 && grow < NN) { g_as2[grow] = ps; g_ad2[grow] = pd; }
    }
}

// ---------------- layer2: single-pass softmax-aggregate + bias → d_out ----------
__global__ void k_node2(const float* __restrict__ b2, float* __restrict__ dout) {
    int lane = threadIdx.x & 31;
    int warp = (blockIdx.x * blockDim.x + threadIdx.x) >> 5;
    int nwarp = (gridDim.x * blockDim.x) >> 5;
    for (int n = warp; n < NN; n += nwarp) {
        int beg = (n == 0) ? 0 : g_off[n - 1];
        int end = g_off[n];
        float ad = g_ad2[n];
        float4 acc = make_float4(0.f, 0.f, 0.f, 0.f);
        float sum = 0.f;
        for (int base = beg; base < end; base += 32) {
            int cnt = end - base; if (cnt > 32) cnt = 32;
            int idx = (lane < cnt) ? g_csrc[base + lane] : 0;
#pragma unroll 4
            for (int j = 0; j < cnt; j++) {
                int s = __shfl_sync(0xffffffffu, idx, j);
                float e = __expf(leaky(g_as2[s] + ad));
                sum += e;
                if (lane < 10) {
                    float4 hv = *(const float4*)&g_h2[s * 40 + lane * 4];
                    acc.x += e * hv.x; acc.y += e * hv.y;
                    acc.z += e * hv.z; acc.w += e * hv.w;
                }
            }
        }
        float inv = (sum > 0.f) ? 1.f / sum : 0.f;
        if (lane < 10) {
            float4 bv = *(const float4*)&b2[lane * 4];
            float4 o;
            o.x = acc.x * inv + bv.x; o.y = acc.y * inv + bv.y;
            o.z = acc.z * inv + bv.z; o.w = acc.w * inv + bv.w;
            *(float4*)&dout[n * 40 + lane * 4] = o;
        }
    }
}

// ---------------- launch ----------------
extern "C" void kernel_launch(void* const* d_in, const int* in_sizes, int n_in,
                              void* d_out, int out_size) {
    const float* x   = (const float*)d_in[0];
    const int*   ei  = (const int*)d_in[1];
    const float* W1  = (const float*)d_in[2];
    const float* as1 = (const float*)d_in[3];
    const float* ad1 = (const float*)d_in[4];
    const float* b1  = (const float*)d_in[5];
    const float* W2  = (const float*)d_in[6];
    const float* as2 = (const float*)d_in[7];
    const float* ad2 = (const float*)d_in[8];
    const float* b2  = (const float*)d_in[9];
    float* out = (float*)d_out;

    k_init<<<(NN + 255) / 256, 256>>>();
    k_deg<<<(NE + 255) / 256, 256>>>(ei);
    k_scan1<<<NB_SCAN, 256>>>();
    k_scan2<<<1, 256>>>();
    k_scan3<<<NB_SCAN, 256>>>();
    k_scatter<<<(NE + 255) / 256, 256>>>(ei);
    k_gemm1<<<(NN + 127) / 128, 256>>>(x, W1, as1, ad1);
    k_node1<<<(NN * 32 + 255) / 256, 256>>>(b1);
    k_gemm2<<<(NN + 127) / 128, 256>>>(W2, as2, ad2);
    k_node2<<<(NN * 32 + 255) / 256, 256>>>(b2, out);
}